// round 1
// baseline (speedup 1.0000x reference)
#include <cuda_runtime.h>
#include <math.h>

// out[b,d] = iw[A-1,d] * sum_a w[a] * hs[b, idx[a], d]
// where idx/counts derive from a Pell-like "spine" and Fibonacci-like path
// counts of `position`, and w[] comes from a tiny 1->64->1 MLP over counts.

__global__ void fla_kernel(const float* __restrict__ hs,
                           const float* __restrict__ iw,
                           const float* __restrict__ w1,
                           const float* __restrict__ b1,
                           const float* __restrict__ w2,
                           const float* __restrict__ b2,
                           const int* __restrict__ pos_p,
                           float* __restrict__ out,
                           int B, int S, int D) {
    __shared__ int   s_idx[20];
    __shared__ int   s_cnt[20];
    __shared__ float s_raw[20];
    __shared__ float s_w[20];
    __shared__ int   s_A;

    const int tid = threadIdx.x;

    // ---- Phase 1: spine / idx / path-counts (thread 0) ----
    if (tid == 0) {
        const int position = pos_p[0];
        int spine[24];
        spine[0] = 0; spine[1] = 1; spine[2] = 2;
        int ns = 3;
        while (spine[ns - 1] < 8192) { spine[ns] = 2 * spine[ns - 1] + spine[ns - 2]; ns++; }
        int A = 0;
        if (position >= 1 && position < ns) {
            for (int t = 0; t < ns; t++) {
                int sp = spine[t];
                if (sp < position && sp < S) {
                    int k = position - sp;            // pc[sp,pos] = a(k): a(1)=1,a(2)=2,a(k)=a(k-1)+a(k-2)
                    long long c;
                    if (k == 1) c = 1;
                    else if (k == 2) c = 2;
                    else {
                        long long p2 = 1, p1 = 2;
                        for (int q = 3; q <= k; q++) { long long cur = p1 + p2; p2 = p1; p1 = cur; }
                        c = p1;
                    }
                    s_idx[A] = sp;
                    s_cnt[A] = (int)c;
                    A++;
                }
            }
        }
        s_A = A;
    }
    __syncthreads();

    const int A = s_A;

    if (A == 0) {
        // reference returns zeros; d_out is poisoned, so write them.
        const int total = B * D;
        for (int i = blockIdx.x * blockDim.x + tid; i < total; i += gridDim.x * blockDim.x)
            out[i] = 0.0f;
        return;
    }

    // ---- Phase 2: tiny MLP, one thread per anchor (A <= 12) ----
    if (tid < A) {
        const float c = (float)s_cnt[tid];
        float a0 = 0.f, a1 = 0.f, a2 = 0.f, a3 = 0.f;
#pragma unroll
        for (int j = 0; j < 64; j += 4) {
            float h0 = fmaxf(fmaf(c, w1[j + 0], b1[j + 0]), 0.f);
            float h1 = fmaxf(fmaf(c, w1[j + 1], b1[j + 1]), 0.f);
            float h2 = fmaxf(fmaf(c, w1[j + 2], b1[j + 2]), 0.f);
            float h3 = fmaxf(fmaf(c, w1[j + 3], b1[j + 3]), 0.f);
            a0 = fmaf(h0, w2[j + 0], a0);
            a1 = fmaf(h1, w2[j + 1], a1);
            a2 = fmaf(h2, w2[j + 2], a2);
            a3 = fmaf(h3, w2[j + 3], a3);
        }
        float x = (a0 + a1) + (a2 + a3) + b2[0];
        // softplus = logaddexp(x, 0)
        float sp = (x > 20.0f) ? x : log1pf(expf(x));
        s_raw[tid] = sp;
    }
    __syncthreads();
    if (tid == 0) {
        float sum = 0.f;
        for (int a = 0; a < A; a++) sum += s_raw[a];
        float inv = 1.0f / sum;
        for (int a = 0; a < A; a++) s_w[a] = s_raw[a] * inv;
    }
    __syncthreads();

    // ---- Phase 3: weighted gather + interference scaling ----
    const float* iw_row = iw + (size_t)(A - 1) * D;

    if ((D & 3) == 0) {
        const int D4 = D >> 2;
        const int total4 = B * D4;
        const float4* iw4 = reinterpret_cast<const float4*>(iw_row);
        float4* out4 = reinterpret_cast<float4*>(out);
        for (int i = blockIdx.x * blockDim.x + tid; i < total4; i += gridDim.x * blockDim.x) {
            const int b  = i / D4;
            const int d4 = i - b * D4;
            const float4* base = reinterpret_cast<const float4*>(hs + (size_t)b * S * D) + d4;
            float4 acc = make_float4(0.f, 0.f, 0.f, 0.f);
            for (int a = 0; a < A; a++) {
                const float w = s_w[a];
                const float4 v = base[(size_t)s_idx[a] * D4];
                acc.x = fmaf(w, v.x, acc.x);
                acc.y = fmaf(w, v.y, acc.y);
                acc.z = fmaf(w, v.z, acc.z);
                acc.w = fmaf(w, v.w, acc.w);
            }
            const float4 g = iw4[d4];
            acc.x *= g.x; acc.y *= g.y; acc.z *= g.z; acc.w *= g.w;
            out4[i] = acc;
        }
    } else {
        const int total = B * D;
        for (int i = blockIdx.x * blockDim.x + tid; i < total; i += gridDim.x * blockDim.x) {
            const int b = i / D;
            const int d = i - b * D;
            float acc = 0.f;
            for (int a = 0; a < A; a++)
                acc = fmaf(s_w[a], hs[(size_t)b * S * D + (size_t)s_idx[a] * D + d], acc);
            out[i] = acc * iw_row[d];
        }
    }
}

extern "C" void kernel_launch(void* const* d_in, const int* in_sizes, int n_in,
                              void* d_out, int out_size) {
    const float* hs  = (const float*)d_in[0];  // (B, S, D)
    const float* iw  = (const float*)d_in[1];  // (10, D)
    const float* w1  = (const float*)d_in[2];  // (64, 1)
    const float* b1  = (const float*)d_in[3];  // (64,)
    const float* w2  = (const float*)d_in[4];  // (1, 64)
    const float* b2  = (const float*)d_in[5];  // (1,)
    const int*   pos = (const int*)d_in[6];    // scalar

    const int D = in_sizes[1] / 10;
    const int B = out_size / D;
    const int S = in_sizes[0] / (B * D);

    float* out = (float*)d_out;

    // B*D/4 float4 elements of work; 256 threads/block.
    int work = (B * D + 3) / 4;
    int blocks = (work + 255) / 256;
    if (blocks < 1) blocks = 1;
    if (blocks > 148) blocks = 148;

    fla_kernel<<<blocks, 256>>>(hs, iw, w1, b1, w2, b2, pos, out, B, S, D);
}

// round 2
// speedup vs baseline: 1.2651x; 1.2651x over previous
#include <cuda_runtime.h>
#include <math.h>

// out[b,d] = iw[A-1,d] * (sum_a spw[a] * hs[b, idx[a], d]) / (sum_a spw[a])
//
// Closed-form structure exploited:
//   spine values < 13 are {0,1,2,5,12}; (sp,position) in pc  <=>  position<13
//   and sp<position, so anchors are always a prefix of {0,1,2,5}  (A<=4), and
//   counts[a] = Fib(position - sp + 1)  -- a constant table.
//
// MLP (1->64->1) is computed per-warp with zero barriers:
//   lane = a*8 + s : anchor a in [0,4), hidden slice s covers units [8s,8s+8).
//   shfl_xor(1,2,4) reduces the 8-lane slice sums; softplus per group;
//   shfl_xor(8,16) sums softplus across the 4 anchor groups.

__device__ __forceinline__ float softplus_f(float x) {
    // numerically stable: max(x,0) + log1p(exp(-|x|))  == logaddexp(x, 0)
    return fmaxf(x, 0.0f) + log1pf(expf(-fabsf(x)));
}

__global__ void __launch_bounds__(128, 1)
fla_kernel(const float* __restrict__ hs,
           const float* __restrict__ iw,
           const float* __restrict__ w1,
           const float* __restrict__ b1,
           const float* __restrict__ w2,
           const float* __restrict__ b2,
           const int* __restrict__ pos_p,
           float* __restrict__ out,
           int B, int S, int D) {
    const int tid  = blockIdx.x * blockDim.x + threadIdx.x;
    const int lane = threadIdx.x & 31;
    const int a    = lane >> 3;   // anchor group 0..3
    const int s    = lane & 7;    // hidden-slice 0..7 (8 units each)

    // ---- head of dependency chain: position ----
    const int position = __ldg(pos_p);

    // ---- MLP weight slice loads (independent of position; issue early) ----
    const float4* w1v = reinterpret_cast<const float4*>(w1);
    const float4* b1v = reinterpret_cast<const float4*>(b1);
    const float4* w2v = reinterpret_cast<const float4*>(w2);
    const float4 w1a = __ldg(&w1v[2 * s]);
    const float4 w1b = __ldg(&w1v[2 * s + 1]);
    const float4 b1a = __ldg(&b1v[2 * s]);
    const float4 b1b = __ldg(&b1v[2 * s + 1]);
    const float4 w2a = __ldg(&w2v[2 * s]);
    const float4 w2b = __ldg(&w2v[2 * s + 1]);
    const float  b2v = __ldg(b2);

    // ---- anchors: constant tables, no loops ----
    const int SP0 = 0, SP1 = 1, SP2 = 2, SP3 = 5;
    int A = 0;
    if (position >= 1 && position < 13) {
        A = (SP0 < position && SP0 < S)
          + (SP1 < position && SP1 < S)
          + (SP2 < position && SP2 < S)
          + (SP3 < position && SP3 < S);
    }

    if (A == 0) {   // reference returns zeros
        const int total = B * D;
        for (int i = tid; i < total; i += gridDim.x * blockDim.x) out[i] = 0.0f;
        return;
    }

    // Fib(k+1) table indexed by k = position - sp, k in [1,12]
    const float fibt[13] = {0.f,1.f,2.f,3.f,5.f,8.f,13.f,21.f,34.f,55.f,89.f,144.f,233.f};
    const int spv[4] = {SP0, SP1, SP2, SP3};
    int k = position - spv[a];
    k = (k < 0) ? 0 : (k > 12 ? 12 : k);
    const float c = fibt[k];

    // ---- issue gather loads NOW (overlap MLP under their latency) ----
    const int D4 = D >> 2;            // D is 1024 in this problem
    const int b_ = tid / D4;
    const int d4 = tid - b_ * D4;
    const bool active = (tid < B * D4);

    float4 v0 = make_float4(0,0,0,0), v1 = v0, v2 = v0, v3 = v0, g = v0;
    if (active) {
        const float4* base = reinterpret_cast<const float4*>(hs + (size_t)b_ * S * D) + d4;
        v0 = __ldg(base + (size_t)SP0 * D4);
        if (A > 1) v1 = __ldg(base + (size_t)SP1 * D4);
        if (A > 2) v2 = __ldg(base + (size_t)SP2 * D4);
        if (A > 3) v3 = __ldg(base + (size_t)SP3 * D4);
        g = __ldg(reinterpret_cast<const float4*>(iw + (size_t)(A - 1) * D) + d4);
    }

    // ---- MLP partial for (anchor a, hidden slice s): 8 units ----
    float p;
    {
        float h0 = fmaxf(fmaf(c, w1a.x, b1a.x), 0.f);
        float h1 = fmaxf(fmaf(c, w1a.y, b1a.y), 0.f);
        float h2 = fmaxf(fmaf(c, w1a.z, b1a.z), 0.f);
        float h3 = fmaxf(fmaf(c, w1a.w, b1a.w), 0.f);
        float h4 = fmaxf(fmaf(c, w1b.x, b1b.x), 0.f);
        float h5 = fmaxf(fmaf(c, w1b.y, b1b.y), 0.f);
        float h6 = fmaxf(fmaf(c, w1b.z, b1b.z), 0.f);
        float h7 = fmaxf(fmaf(c, w1b.w, b1b.w), 0.f);
        float q0 = h0 * w2a.x + h1 * w2a.y;
        float q1 = h2 * w2a.z + h3 * w2a.w;
        float q2 = h4 * w2b.x + h5 * w2b.y;
        float q3 = h6 * w2b.z + h7 * w2b.w;
        p = (q0 + q1) + (q2 + q3);
    }
    // reduce 8-lane slice group
    p += __shfl_xor_sync(0xffffffffu, p, 1);
    p += __shfl_xor_sync(0xffffffffu, p, 2);
    p += __shfl_xor_sync(0xffffffffu, p, 4);

    float spw = (a < A) ? softplus_f(p + b2v) : 0.0f;

    // sum softplus across the 4 anchor groups (spw replicated within group)
    float ssum = spw;
    ssum += __shfl_xor_sync(0xffffffffu, ssum, 8);
    ssum += __shfl_xor_sync(0xffffffffu, ssum, 16);

    const float wa0 = __shfl_sync(0xffffffffu, spw, 0);
    const float wa1 = __shfl_sync(0xffffffffu, spw, 8);
    const float wa2 = __shfl_sync(0xffffffffu, spw, 16);
    const float wa3 = __shfl_sync(0xffffffffu, spw, 24);
    const float inv = __frcp_rn(ssum);

    if (active) {
        float4 acc;
        acc.x = wa0 * v0.x; acc.y = wa0 * v0.y; acc.z = wa0 * v0.z; acc.w = wa0 * v0.w;
        acc.x = fmaf(wa1, v1.x, acc.x); acc.y = fmaf(wa1, v1.y, acc.y);
        acc.z = fmaf(wa1, v1.z, acc.z); acc.w = fmaf(wa1, v1.w, acc.w);
        acc.x = fmaf(wa2, v2.x, acc.x); acc.y = fmaf(wa2, v2.y, acc.y);
        acc.z = fmaf(wa2, v2.z, acc.z); acc.w = fmaf(wa2, v2.w, acc.w);
        acc.x = fmaf(wa3, v3.x, acc.x); acc.y = fmaf(wa3, v3.y, acc.y);
        acc.z = fmaf(wa3, v3.z, acc.z); acc.w = fmaf(wa3, v3.w, acc.w);
        const float sx = g.x * inv, sy = g.y * inv, sz = g.z * inv, sw = g.w * inv;
        float4 r = make_float4(acc.x * sx, acc.y * sy, acc.z * sz, acc.w * sw);
        reinterpret_cast<float4*>(out)[tid] = r;
    }
}

// Fallback for D not divisible by 4 (not hit for this problem's shapes).
__global__ void fla_kernel_scalar(const float* __restrict__ hs,
                                  const float* __restrict__ iw,
                                  const float* __restrict__ w1,
                                  const float* __restrict__ b1,
                                  const float* __restrict__ w2,
                                  const float* __restrict__ b2,
                                  const int* __restrict__ pos_p,
                                  float* __restrict__ out,
                                  int B, int S, int D) {
    const int position = __ldg(pos_p);
    const int SPV[4] = {0, 1, 2, 5};
    int A = 0;
    if (position >= 1 && position < 13)
        for (int t = 0; t < 4; t++) A += (SPV[t] < position && SPV[t] < S);
    const int total = B * D;
    const int tid = blockIdx.x * blockDim.x + threadIdx.x;
    if (A == 0) {
        for (int i = tid; i < total; i += gridDim.x * blockDim.x) out[i] = 0.0f;
        return;
    }
    const float fibt[13] = {0.f,1.f,2.f,3.f,5.f,8.f,13.f,21.f,34.f,55.f,89.f,144.f,233.f};
    float spw[4], ssum = 0.f;
    for (int t = 0; t < 4; t++) {
        if (t < A) {
            float c = fibt[position - SPV[t]];
            float acc = 0.f;
            for (int j = 0; j < 64; j++)
                acc = fmaf(fmaxf(fmaf(c, w1[j], b1[j]), 0.f), w2[j], acc);
            float x = acc + b2[0];
            spw[t] = fmaxf(x, 0.f) + log1pf(expf(-fabsf(x)));
        } else spw[t] = 0.f;
        ssum += spw[t];
    }
    const float inv = 1.0f / ssum;
    const float* iwr = iw + (size_t)(A - 1) * D;
    for (int i = tid; i < total; i += gridDim.x * blockDim.x) {
        int b = i / D, d = i - b * D;
        float acc = 0.f;
        for (int t = 0; t < A; t++)
            acc = fmaf(spw[t], hs[(size_t)b * S * D + (size_t)SPV[t] * D + d], acc);
        out[i] = acc * iwr[d] * inv;
    }
}

extern "C" void kernel_launch(void* const* d_in, const int* in_sizes, int n_in,
                              void* d_out, int out_size) {
    const float* hs  = (const float*)d_in[0];  // (B, S, D)
    const float* iw  = (const float*)d_in[1];  // (10, D)
    const float* w1  = (const float*)d_in[2];  // (64, 1)
    const float* b1  = (const float*)d_in[3];  // (64,)
    const float* w2  = (const float*)d_in[4];  // (1, 64)
    const float* b2  = (const float*)d_in[5];  // (1,)
    const int*   pos = (const int*)d_in[6];    // scalar

    const int D = in_sizes[1] / 10;
    const int B = out_size / D;
    const int S = in_sizes[0] / (B * D);
    float* out = (float*)d_out;

    if ((D & 3) == 0) {
        const int total4 = B * (D >> 2);
        const int blocks = (total4 + 127) / 128;
        fla_kernel<<<blocks, 128>>>(hs, iw, w1, b1, w2, b2, pos, out, B, S, D);
    } else {
        const int total = B * D;
        int blocks = (total + 255) / 256;
        if (blocks > 148) blocks = 148;
        fla_kernel_scalar<<<blocks, 256>>>(hs, iw, w1, b1, w2, b2, pos, out, B, S, D);
    }
}